// round 13
// baseline (speedup 1.0000x reference)
#include <cuda_runtime.h>
#include <math.h>

// ---------------------------------------------------------------------------
// PoseConvLSTM, R13: R12 gate-split fused design, with chunk input staging
// moved from register-staged LDG+STS to zero-fill cp.async (cp4z) direct to
// smem. Frees ~10 regs (ist array) and removes the store-back pass.
// Compute loop identical to R12 (validated: 8.59 ms, fma 51%).
// ---------------------------------------------------------------------------

#define NPIX 4096
#define TT 128

typedef unsigned long long ull;

// ----- scratch -----
__device__ float g_ys1[TT * 32 * NPIX];
__device__ float g_ys2[TT * 64 * NPIX];
__device__ float g_c1[32 * NPIX];
__device__ float g_c2[64 * NPIX];
__device__ float g_zerobuf[64 * NPIX];
// packed weights: [co][cin][gatepair(2)][tap-pairs: 10 ull = 20 floats]
// gatepair 0 = {i,f}, 1 = {o,g}; tap t at float offset 2t; floats 18..19 pad
__device__ __align__(16) float g_w1p[32 * 35 * 40];
__device__ __align__(16) float g_w2p[64 * 96 * 40];
__device__ float g_fcpart[64 * TT * 6];

__device__ __forceinline__ float sigmf(float x) {
    return 1.0f / (1.0f + __expf(-x));
}
__device__ __forceinline__ float tanh_f(float x) {
    return 1.0f - 2.0f / (__expf(2.0f * x) + 1.0f);
}

__device__ __forceinline__ ull pack2(float lo, float hi) {
    ull r;
    asm("mov.b64 %0, {%1, %2};" : "=l"(r) : "f"(lo), "f"(hi));
    return r;
}
__device__ __forceinline__ ull dup2(float v) {
    ull r;
    asm("mov.b64 %0, {%1, %1};" : "=l"(r) : "f"(v));
    return r;
}
__device__ __forceinline__ void unpack2(ull p, float& lo, float& hi) {
    asm("mov.b64 {%0, %1}, %2;" : "=f"(lo), "=f"(hi) : "l"(p));
}
__device__ __forceinline__ ull ffma2(ull a, ull b, ull c) {
    ull d;
    asm("fma.rn.f32x2 %0, %1, %2, %3;" : "=l"(d) : "l"(a), "l"(b), "l"(c));
    return d;
}
__device__ __forceinline__ unsigned smem_u32(const void* p) {
    return (unsigned)__cvta_generic_to_shared(p);
}
__device__ __forceinline__ void cp16(unsigned s, const void* g) {
    asm volatile("cp.async.cg.shared.global [%0], [%1], 16;"
                 :: "r"(s), "l"(g) : "memory");
}
// 4-byte cp.async with zero-fill: src_size = 0 -> dst gets zeros
__device__ __forceinline__ void cp4z(unsigned s, const void* g, int sz) {
    asm volatile("cp.async.ca.shared.global [%0], [%1], 4, %2;"
                 :: "r"(s), "l"(g), "r"(sz) : "memory");
}
__device__ __forceinline__ void cp_commit() {
    asm volatile("cp.async.commit_group;" ::: "memory");
}
__device__ __forceinline__ void cp_wait0() {
    asm volatile("cp.async.wait_group 0;" ::: "memory");
}

// ----- merged setup (1 launch): zero states + repack to gate-pair layout --
__global__ void setup_kernel(const float* __restrict__ w1,
                             const float* __restrict__ w2,
                             float* __restrict__ w1p, float* __restrict__ w2p,
                             float* __restrict__ c1, float* __restrict__ c2,
                             float* __restrict__ zb) {
    int i = blockIdx.x * blockDim.x + threadIdx.x;
    const int N_C1 = 32 * NPIX;
    const int N_C2 = 64 * NPIX;
    const int N_W1 = 32 * 35 * 40;
    const int N_W2 = 64 * 96 * 40;
    if (i < N_C1) { c1[i] = 0.0f; return; }
    i -= N_C1;
    if (i < N_C2) { c2[i] = 0.0f; return; }
    i -= N_C2;
    if (i < N_C2) { zb[i] = 0.0f; return; }
    i -= N_C2;
    if (i < N_W1) {
        int t2 = i % 20;
        int r = i / 20;
        int gp = r & 1; r >>= 1;
        int cin = r % 35; int co = r / 35;
        float v = 0.0f;
        if (t2 < 18) {
            int tap = t2 >> 1;
            int gate = gp * 2 + (t2 & 1);
            v = w1[((gate * 32 + co) * 35 + cin) * 9 + tap];
        }
        w1p[i] = v;
        return;
    }
    i -= N_W1;
    if (i < N_W2) {
        int t2 = i % 20;
        int r = i / 20;
        int gp = r & 1; r >>= 1;
        int cin = r % 96; int co = r / 96;
        float v = 0.0f;
        if (t2 < 18) {
            int tap = t2 >> 1;
            int gate = gp * 2 + (t2 & 1);
            v = w2[((gate * 64 + co) * 96 + cin) * 9 + tap];
        }
        w2p[i] = v;
        return;
    }
}

// ----- ConvLSTM step body: 8x8 tile, gate-split lane pairs ---------------
// lane l: gp = l&1 (gate pair), pr = l>>1; pr -> x-group (pr&1)*4, row pr>>1.
// Each lane computes its 2 gates for 4 pixels (1x4 strip).
template <int HC, int CIN, int CX, int CCH>
__device__ __forceinline__ void lstm_body(
    int bx, float* sbuf,
    const float* __restrict__ xin,
    const float* __restrict__ hprev,
    const float* __restrict__ wp,
    const float* __restrict__ bias,
    float* __restrict__ cst,
    float* __restrict__ hout)
{
    constexpr int SROW = 12;
    constexpr int SPLANE = 120;              // 10 rows * 12
    constexpr int HWIN = 100;                // 10x10 halo
    constexpr int NCH = CIN / CCH;
    constexpr int IN_FL = CCH * SPLANE;
    constexpr int W_FL = 8 * CCH * 40;       // floats
    constexpr int BUFSZ = IN_FL + W_FL;
    constexpr int ICNT = CCH * HWIN;
    constexpr int WCNT4 = W_FL / 4;          // float4 count = 8*CCH*10

    const int tid = threadIdx.x;
    const int tile = bx & 63;
    const int cog = bx >> 6;
    const int tx0 = (tile & 7) * 8;
    const int ty0 = (tile >> 3) * 8;
    const int co_l = tid >> 5;
    const int l = tid & 31;
    const int gp = l & 1;
    const int pr = l >> 1;
    const int x0 = (pr & 1) * 4;
    const int py = pr >> 1;
    const int co0 = cog << 3;
    const int co = co0 + co_l;

    const float4* __restrict__ wsrc = reinterpret_cast<const float4*>(wp);

    // async halo + weight stage for chunk starting at absolute cin0
    auto stage_chunk = [&](float* dst, int cin0) {
        for (int idx = tid; idx < ICNT; idx += 256) {
            int cin_l = idx / HWIN;
            int r = idx - cin_l * HWIN;
            int ly = r / 10;
            int lx = r - ly * 10;
            int gy = ty0 + ly - 1;
            int gx = tx0 + lx - 1;
            int ok = ((unsigned)gy < 64u && (unsigned)gx < 64u) ? 4 : 0;
            int ac = cin0 + cin_l;
            const float* src = (ac < CX) ? (xin + ac * NPIX)
                                         : (hprev + (ac - CX) * NPIX);
            const float* g = ok ? (src + gy * 64 + gx) : src;
            cp4z(smem_u32(dst + cin_l * SPLANE + ly * SROW + lx), g, ok);
        }
        for (int d = tid; d < WCNT4; d += 256) {
            int cl_co = d / (CCH * 10);
            int rr = d - cl_co * (CCH * 10);
            const float4* g = wsrc +
                ((size_t)(co0 + cl_co) * CIN + cin0) * 10 + rr;
            cp16(smem_u32(reinterpret_cast<float4*>(dst + IN_FL) + d), g);
        }
        cp_commit();
    };

    // ---- chunk 0 ----
    stage_chunk(sbuf, 0);
    cp_wait0();
    __syncthreads();

    // acc[j] = {z_g0, z_g1} of this lane's gate pair for pixel j (0..3)
    ull acc[4];
    {
        ull b = pack2(bias[(gp * 2) * HC + co], bias[(gp * 2 + 1) * HC + co]);
#pragma unroll
        for (int j = 0; j < 4; ++j) acc[j] = b;
    }

    for (int ch = 0; ch < NCH; ++ch) {
        float* buf = sbuf + ((NCH > 1) ? (ch & 1) * BUFSZ : 0);
        float* nbuf = sbuf + ((NCH > 1) ? ((ch + 1) & 1) * BUFSZ : 0);
        const bool pf = (NCH > 1) && (ch + 1 < NCH);

        if (pf) stage_chunk(nbuf, (ch + 1) * CCH);

        // ---- compute: per cin, weights 4xLDS.128+1xLDS.64 (per-lane 72B),
        //      input float4+float2 per ky (pair-broadcast), 36 FFMA2 ----
        const float* wbase = buf + IN_FL + co_l * (CCH * 40) + gp * 20;
        const float* sb = buf + py * SROW + x0;
#pragma unroll 1
        for (int cl = 0; cl < CCH; ++cl) {
            const float* wl = wbase + cl * 40;
            const ulonglong2* wq = reinterpret_cast<const ulonglong2*>(wl);
            ulonglong2 wA = wq[0];   // taps 0,1
            ulonglong2 wB = wq[1];   // taps 2,3
            ulonglong2 wC = wq[2];   // taps 4,5
            ulonglong2 wD = wq[3];   // taps 6,7
            ull w8 = *reinterpret_cast<const ull*>(wl + 16);   // tap 8
            ull wt0 = wA.x, wt1 = wA.y, wt2 = wB.x;
            ull wt3 = wB.y, wt4 = wC.x, wt5 = wC.y;
            ull wt6 = wD.x, wt7 = wD.y;

            const float* sr = sb + cl * SPLANE;
            {   // ky = 0
                float4 a = *reinterpret_cast<const float4*>(sr);
                float2 b = *reinterpret_cast<const float2*>(sr + 4);
                ull i0 = dup2(a.x), i1 = dup2(a.y), i2 = dup2(a.z);
                ull i3 = dup2(a.w), i4 = dup2(b.x), i5 = dup2(b.y);
                acc[0] = ffma2(i0, wt0, acc[0]);
                acc[1] = ffma2(i1, wt0, acc[1]);
                acc[2] = ffma2(i2, wt0, acc[2]);
                acc[3] = ffma2(i3, wt0, acc[3]);
                acc[0] = ffma2(i1, wt1, acc[0]);
                acc[1] = ffma2(i2, wt1, acc[1]);
                acc[2] = ffma2(i3, wt1, acc[2]);
                acc[3] = ffma2(i4, wt1, acc[3]);
                acc[0] = ffma2(i2, wt2, acc[0]);
                acc[1] = ffma2(i3, wt2, acc[1]);
                acc[2] = ffma2(i4, wt2, acc[2]);
                acc[3] = ffma2(i5, wt2, acc[3]);
            }
            {   // ky = 1
                float4 a = *reinterpret_cast<const float4*>(sr + SROW);
                float2 b = *reinterpret_cast<const float2*>(sr + SROW + 4);
                ull i0 = dup2(a.x), i1 = dup2(a.y), i2 = dup2(a.z);
                ull i3 = dup2(a.w), i4 = dup2(b.x), i5 = dup2(b.y);
                acc[0] = ffma2(i0, wt3, acc[0]);
                acc[1] = ffma2(i1, wt3, acc[1]);
                acc[2] = ffma2(i2, wt3, acc[2]);
                acc[3] = ffma2(i3, wt3, acc[3]);
                acc[0] = ffma2(i1, wt4, acc[0]);
                acc[1] = ffma2(i2, wt4, acc[1]);
                acc[2] = ffma2(i3, wt4, acc[2]);
                acc[3] = ffma2(i4, wt4, acc[3]);
                acc[0] = ffma2(i2, wt5, acc[0]);
                acc[1] = ffma2(i3, wt5, acc[1]);
                acc[2] = ffma2(i4, wt5, acc[2]);
                acc[3] = ffma2(i5, wt5, acc[3]);
            }
            {   // ky = 2
                float4 a = *reinterpret_cast<const float4*>(sr + 2 * SROW);
                float2 b = *reinterpret_cast<const float2*>(sr + 2 * SROW + 4);
                ull i0 = dup2(a.x), i1 = dup2(a.y), i2 = dup2(a.z);
                ull i3 = dup2(a.w), i4 = dup2(b.x), i5 = dup2(b.y);
                acc[0] = ffma2(i0, wt6, acc[0]);
                acc[1] = ffma2(i1, wt6, acc[1]);
                acc[2] = ffma2(i2, wt6, acc[2]);
                acc[3] = ffma2(i3, wt6, acc[3]);
                acc[0] = ffma2(i1, wt7, acc[0]);
                acc[1] = ffma2(i2, wt7, acc[1]);
                acc[2] = ffma2(i3, wt7, acc[2]);
                acc[3] = ffma2(i4, wt7, acc[3]);
                acc[0] = ffma2(i2, w8, acc[0]);
                acc[1] = ffma2(i3, w8, acc[1]);
                acc[2] = ffma2(i4, w8, acc[2]);
                acc[3] = ffma2(i5, w8, acc[3]);
            }
        }

        if (pf) cp_wait0();
        if (NCH > 1) __syncthreads();
    }

    // ---- epilogue: exchange gate pairs within the lane pair ----
    ull oth[4];
#pragma unroll
    for (int j = 0; j < 4; ++j)
        oth[j] = __shfl_xor_sync(0xffffffffu, acc[j], 1);

    const int gy = ty0 + py;
    const int base = co * NPIX + gy * 64 + tx0 + x0 + gp * 2;  // 2 px/lane
    float2 cv = *reinterpret_cast<const float2*>(cst + base);
    float cold[2] = {cv.x, cv.y};
    float cn[2], hv[2];
#pragma unroll
    for (int j2 = 0; j2 < 2; ++j2) {
        int j = gp * 2 + j2;
        float zi, zf, zo, zg;
        if (gp == 0) {
            unpack2(acc[j], zi, zf);
            unpack2(oth[j], zo, zg);
        } else {
            unpack2(oth[j], zi, zf);
            unpack2(acc[j], zo, zg);
        }
        float ig = sigmf(zi);
        float fg = sigmf(zf);
        float og = sigmf(zo);
        float gg = tanh_f(zg);
        float c = fmaf(fg, cold[j2], ig * gg);
        cn[j2] = c;
        hv[j2] = og * tanh_f(c);
    }
    *reinterpret_cast<float2*>(cst + base) = make_float2(cn[0], cn[1]);
    *reinterpret_cast<float2*>(hout + base) = make_float2(hv[0], hv[1]);
}

// ----- standalone step kernels (t=0 L1, t=127 L2) -----
template <int HC, int CIN, int CX, int CCH>
__global__ void __launch_bounds__(256, 3) lstm_step(
    const float* __restrict__ xin, const float* __restrict__ hprev,
    const float* __restrict__ wp, const float* __restrict__ bias,
    float* __restrict__ cst, float* __restrict__ hout)
{
    extern __shared__ float sbuf[];
    lstm_body<HC, CIN, CX, CCH>(blockIdx.x, sbuf, xin, hprev, wp, bias,
                                cst, hout);
}

// ----- fused: blocks [0,512) = L2[t]; [512,768) = L1[t+1] -----
__global__ void __launch_bounds__(256, 3) fused_step(
    const float* __restrict__ ys1_t,
    const float* __restrict__ ys2_prev,
    const float* __restrict__ w2p, const float* __restrict__ b2,
    float* __restrict__ c2, float* __restrict__ ys2_t,
    const float* __restrict__ x_next,
    const float* __restrict__ w1p, const float* __restrict__ b1,
    float* __restrict__ c1, float* __restrict__ ys1_next)
{
    extern __shared__ float sbuf[];
    int bx = blockIdx.x;
    if (bx < 512) {
        lstm_body<64, 96, 32, 16>(bx, sbuf, ys1_t, ys2_prev, w2p, b2,
                                  c2, ys2_t);
    } else {
        lstm_body<32, 35, 3, 35>(bx - 512, sbuf, x_next, ys1_t, w1p, b1,
                                 c1, ys1_next);
    }
}

// ----- FC pass 1: k-chunk partials -----
__global__ void __launch_bounds__(256) fc_part(const float* __restrict__ ys2,
                                               const float* __restrict__ fw,
                                               float* __restrict__ part) {
    __shared__ float red[8][6];
    const int kc = blockIdx.x;
    const int tid = threadIdx.x;
    const int lane = tid & 31;
    const int warp = tid >> 5;
    const int k0 = kc * 4096;
    const int NK = 64 * NPIX;

    for (int t = 0; t < TT; ++t) {
        const float* y = ys2 + (size_t)t * NK + k0;
        float acc[6] = {0.f, 0.f, 0.f, 0.f, 0.f, 0.f};
#pragma unroll 4
        for (int k = tid; k < 4096; k += 256) {
            float v = y[k];
#pragma unroll
            for (int j = 0; j < 6; ++j)
                acc[j] = fmaf(v, fw[(size_t)j * NK + k0 + k], acc[j]);
        }
#pragma unroll
        for (int j = 0; j < 6; ++j) {
#pragma unroll
            for (int off = 16; off > 0; off >>= 1)
                acc[j] += __shfl_xor_sync(0xffffffffu, acc[j], off);
        }
        if (lane < 6) red[warp][lane] = acc[lane];
        __syncthreads();
        if (tid < 6) {
            float s = 0.0f;
#pragma unroll
            for (int w = 0; w < 8; ++w) s += red[w][tid];
            part[(kc * TT + t) * 6 + tid] = s;
        }
        __syncthreads();
    }
}

// ----- FC pass 2 -----
__global__ void fc_reduce(const float* __restrict__ part,
                          const float* __restrict__ fb,
                          float* __restrict__ out) {
    int i = blockIdx.x * blockDim.x + threadIdx.x;
    if (i >= TT * 6) return;
    int j = i % 6;
    float s = fb[j];
    for (int kc = 0; kc < 64; ++kc) s += part[kc * TT * 6 + i];
    out[i] = s;
}

// ----- pack final states -----
__global__ void finalize_kernel(const float* __restrict__ ys1,
                                const float* __restrict__ c1,
                                const float* __restrict__ ys2,
                                const float* __restrict__ c2,
                                float* __restrict__ out) {
    int i = blockIdx.x * blockDim.x + threadIdx.x;
    const int N1 = 32 * NPIX;
    const int N2 = 64 * NPIX;
    if (i < N1) {
        out[768 + i] = ys1[(size_t)(TT - 1) * N1 + i];
    } else if (i < 2 * N1) {
        out[768 + i] = c1[i - N1];
    } else if (i < 2 * N1 + N2) {
        out[768 + i] = ys2[(size_t)(TT - 1) * N2 + (i - 2 * N1)];
    } else if (i < 2 * N1 + 2 * N2) {
        out[768 + i] = c2[i - 2 * N1 - N2];
    }
}

extern "C" void kernel_launch(void* const* d_in, const int* in_sizes, int n_in,
                              void* d_out, int out_size) {
    const float* input = (const float*)d_in[0];
    const float* w1    = (const float*)d_in[1];
    const float* b1    = (const float*)d_in[2];
    const float* w2    = (const float*)d_in[3];
    const float* b2    = (const float*)d_in[4];
    const float* fcw   = (const float*)d_in[5];
    const float* fcb   = (const float*)d_in[6];
    float* out = (float*)d_out;

    float *ys1, *ys2, *c1, *c2, *zb, *w1p, *w2p, *fcpart;
    cudaGetSymbolAddress((void**)&ys1, g_ys1);
    cudaGetSymbolAddress((void**)&ys2, g_ys2);
    cudaGetSymbolAddress((void**)&c1, g_c1);
    cudaGetSymbolAddress((void**)&c2, g_c2);
    cudaGetSymbolAddress((void**)&zb, g_zerobuf);
    cudaGetSymbolAddress((void**)&w1p, g_w1p);
    cudaGetSymbolAddress((void**)&w2p, g_w2p);
    cudaGetSymbolAddress((void**)&fcpart, g_fcpart);

    // L1 (CCH=35, single chunk): (35*120 + 8*35*40)*4 = 61600 B
    // L2 (CCH=16, double buf):   2*(16*120 + 8*16*40)*4 = 56320 B
    const int smL1 = (35 * 120 + 8 * 35 * 40) * 4;
    const int smL2 = 2 * (16 * 120 + 8 * 16 * 40) * 4;
    const int smF = smL1 > smL2 ? smL1 : smL2;   // 61600 -> 3 blocks/SM
    cudaFuncSetAttribute((const void*)lstm_step<32, 35, 3, 35>,
                         cudaFuncAttributeMaxDynamicSharedMemorySize, smL1);
    cudaFuncSetAttribute((const void*)lstm_step<64, 96, 32, 16>,
                         cudaFuncAttributeMaxDynamicSharedMemorySize, smL2);
    cudaFuncSetAttribute((const void*)fused_step,
                         cudaFuncAttributeMaxDynamicSharedMemorySize, smF);

    const int NSETUP = 32 * NPIX + 3 * 64 * NPIX + 32 * 35 * 40 + 64 * 96 * 40;
    setup_kernel<<<(NSETUP + 255) / 256, 256>>>(w1, w2, w1p, w2p, c1, c2, zb);

    // t = 0 layer 1 (h0 = 0): 64 tiles * 4 cogroups = 256 blocks
    lstm_step<32, 35, 3, 35><<<256, 256, smL1>>>(input, zb, w1p, b1, c1, ys1);

    // fused steps: L2[t] + L1[t+1], t = 0..126
    for (int t = 0; t < TT - 1; ++t) {
        const float* y1t = ys1 + (size_t)t * 32 * NPIX;
        const float* y2p = (t == 0) ? zb : (ys2 + (size_t)(t - 1) * 64 * NPIX);
        float* y2t = ys2 + (size_t)t * 64 * NPIX;
        const float* xn = input + (size_t)(t + 1) * 3 * NPIX;
        float* y1n = ys1 + (size_t)(t + 1) * 32 * NPIX;
        fused_step<<<768, 256, smF>>>(y1t, y2p, w2p, b2, c2, y2t,
                                      xn, w1p, b1, c1, y1n);
    }

    // t = 127 layer 2: 64 tiles * 8 cogroups = 512 blocks
    lstm_step<64, 96, 32, 16><<<512, 256, smL2>>>(
        ys1 + (size_t)(TT - 1) * 32 * NPIX,
        ys2 + (size_t)(TT - 2) * 64 * NPIX,
        w2p, b2, c2, ys2 + (size_t)(TT - 1) * 64 * NPIX);

    fc_part<<<64, 256>>>(ys2, fcw, fcpart);
    fc_reduce<<<3, 256>>>(fcpart, fcb, out);

    const int NFIN = 2 * 32 * NPIX + 2 * 64 * NPIX;
    finalize_kernel<<<(NFIN + 255) / 256, 256>>>(ys1, c1, ys2, c2, out);
}

// round 14
// speedup vs baseline: 1.0266x; 1.0266x over previous
#include <cuda_runtime.h>
#include <math.h>

// ---------------------------------------------------------------------------
// PoseConvLSTM, R14: R12 gate-split fused design (register-staged prefetch,
// validated 8.59 ms) + unroll-2 on the cin compute loop. With gate-split the
// per-iteration live set (9 wt ull + 6 in ull) x2 + 4 acc fits the 85-reg
// cap, letting ptxas batch next-iteration LDS under current FFMA2s.
// ---------------------------------------------------------------------------

#define NPIX 4096
#define TT 128

typedef unsigned long long ull;

// ----- scratch -----
__device__ float g_ys1[TT * 32 * NPIX];
__device__ float g_ys2[TT * 64 * NPIX];
__device__ float g_c1[32 * NPIX];
__device__ float g_c2[64 * NPIX];
__device__ float g_zerobuf[64 * NPIX];
// packed weights: [co][cin][gatepair(2)][tap-pairs: 10 ull = 20 floats]
__device__ __align__(16) float g_w1p[32 * 35 * 40];
__device__ __align__(16) float g_w2p[64 * 96 * 40];
__device__ float g_fcpart[64 * TT * 6];

__device__ __forceinline__ float sigmf(float x) {
    return 1.0f / (1.0f + __expf(-x));
}
__device__ __forceinline__ float tanh_f(float x) {
    return 1.0f - 2.0f / (__expf(2.0f * x) + 1.0f);
}

__device__ __forceinline__ ull pack2(float lo, float hi) {
    ull r;
    asm("mov.b64 %0, {%1, %2};" : "=l"(r) : "f"(lo), "f"(hi));
    return r;
}
__device__ __forceinline__ ull dup2(float v) {
    ull r;
    asm("mov.b64 %0, {%1, %1};" : "=l"(r) : "f"(v));
    return r;
}
__device__ __forceinline__ void unpack2(ull p, float& lo, float& hi) {
    asm("mov.b64 {%0, %1}, %2;" : "=f"(lo), "=f"(hi) : "l"(p));
}
__device__ __forceinline__ ull ffma2(ull a, ull b, ull c) {
    ull d;
    asm("fma.rn.f32x2 %0, %1, %2, %3;" : "=l"(d) : "l"(a), "l"(b), "l"(c));
    return d;
}
__device__ __forceinline__ unsigned smem_u32(const void* p) {
    return (unsigned)__cvta_generic_to_shared(p);
}
__device__ __forceinline__ void cp16(unsigned s, const void* g) {
    asm volatile("cp.async.cg.shared.global [%0], [%1], 16;"
                 :: "r"(s), "l"(g) : "memory");
}
__device__ __forceinline__ void cp_commit() {
    asm volatile("cp.async.commit_group;" ::: "memory");
}
__device__ __forceinline__ void cp_wait0() {
    asm volatile("cp.async.wait_group 0;" ::: "memory");
}

// ----- merged setup (1 launch): zero states + repack to gate-pair layout --
__global__ void setup_kernel(const float* __restrict__ w1,
                             const float* __restrict__ w2,
                             float* __restrict__ w1p, float* __restrict__ w2p,
                             float* __restrict__ c1, float* __restrict__ c2,
                             float* __restrict__ zb) {
    int i = blockIdx.x * blockDim.x + threadIdx.x;
    const int N_C1 = 32 * NPIX;
    const int N_C2 = 64 * NPIX;
    const int N_W1 = 32 * 35 * 40;
    const int N_W2 = 64 * 96 * 40;
    if (i < N_C1) { c1[i] = 0.0f; return; }
    i -= N_C1;
    if (i < N_C2) { c2[i] = 0.0f; return; }
    i -= N_C2;
    if (i < N_C2) { zb[i] = 0.0f; return; }
    i -= N_C2;
    if (i < N_W1) {
        int t2 = i % 20;
        int r = i / 20;
        int gp = r & 1; r >>= 1;
        int cin = r % 35; int co = r / 35;
        float v = 0.0f;
        if (t2 < 18) {
            int tap = t2 >> 1;
            int gate = gp * 2 + (t2 & 1);
            v = w1[((gate * 32 + co) * 35 + cin) * 9 + tap];
        }
        w1p[i] = v;
        return;
    }
    i -= N_W1;
    if (i < N_W2) {
        int t2 = i % 20;
        int r = i / 20;
        int gp = r & 1; r >>= 1;
        int cin = r % 96; int co = r / 96;
        float v = 0.0f;
        if (t2 < 18) {
            int tap = t2 >> 1;
            int gate = gp * 2 + (t2 & 1);
            v = w2[((gate * 64 + co) * 96 + cin) * 9 + tap];
        }
        w2p[i] = v;
        return;
    }
}

// ----- ConvLSTM step body: 8x8 tile, gate-split lane pairs ---------------
template <int HC, int CIN, int CX, int CCH>
__device__ __forceinline__ void lstm_body(
    int bx, float* sbuf,
    const float* __restrict__ xin,
    const float* __restrict__ hprev,
    const float* __restrict__ wp,
    const float* __restrict__ bias,
    float* __restrict__ cst,
    float* __restrict__ hout)
{
    constexpr int SROW = 12;
    constexpr int SPLANE = 120;
    constexpr int HWIN = 100;
    constexpr int NCH = CIN / CCH;
    constexpr int IN_FL = CCH * SPLANE;
    constexpr int W_FL = 8 * CCH * 40;
    constexpr int BUFSZ = IN_FL + W_FL;
    constexpr int ICNT = CCH * HWIN;
    constexpr int WCNT4 = W_FL / 4;
    constexpr int IR = (ICNT + 255) / 256;

    const int tid = threadIdx.x;
    const int tile = bx & 63;
    const int cog = bx >> 6;
    const int tx0 = (tile & 7) * 8;
    const int ty0 = (tile >> 3) * 8;
    const int co_l = tid >> 5;
    const int l = tid & 31;
    const int gp = l & 1;
    const int pr = l >> 1;
    const int x0 = (pr & 1) * 4;
    const int py = pr >> 1;
    const int co0 = cog << 3;
    const int co = co0 + co_l;

    const float4* __restrict__ wsrc = reinterpret_cast<const float4*>(wp);

    // ---- load chunk 0 ----
    for (int idx = tid; idx < ICNT; idx += 256) {
        int cin_l = idx / HWIN;
        int r = idx - cin_l * HWIN;
        int ly = r / 10;
        int lx = r - ly * 10;
        int gy = ty0 + ly - 1;
        int gx = tx0 + lx - 1;
        float v = 0.0f;
        if ((unsigned)gy < 64u && (unsigned)gx < 64u) {
            const float* src = (cin_l < CX) ? (xin + cin_l * NPIX)
                                            : (hprev + (cin_l - CX) * NPIX);
            v = src[gy * 64 + gx];
        }
        sbuf[cin_l * SPLANE + ly * SROW + lx] = v;
    }
    for (int d = tid; d < WCNT4; d += 256) {
        int cl_co = d / (CCH * 10);
        int rr = d - cl_co * (CCH * 10);
        const float4* g = wsrc + ((size_t)(co0 + cl_co) * CIN) * 10 + rr;
        cp16(smem_u32(reinterpret_cast<float4*>(sbuf + IN_FL) + d), g);
    }
    cp_commit();
    cp_wait0();
    __syncthreads();

    ull acc[4];
    {
        ull b = pack2(bias[(gp * 2) * HC + co], bias[(gp * 2 + 1) * HC + co]);
#pragma unroll
        for (int j = 0; j < 4; ++j) acc[j] = b;
    }

    for (int ch = 0; ch < NCH; ++ch) {
        float* buf = sbuf + ((NCH > 1) ? (ch & 1) * BUFSZ : 0);
        float* nbuf = sbuf + ((NCH > 1) ? ((ch + 1) & 1) * BUFSZ : 0);
        const bool pf = (NCH > 1) && (ch + 1 < NCH);

        // prefetch next chunk: input into regs (LDG), weights via cp.async
        float ist[IR];
        if (pf) {
            const int cin0n = (ch + 1) * CCH;
#pragma unroll
            for (int r = 0; r < IR; ++r) {
                int idx = tid + r * 256;
                float v = 0.0f;
                if (idx < ICNT) {
                    int cin_l = idx / HWIN;
                    int rr = idx - cin_l * HWIN;
                    int ly = rr / 10;
                    int lx = rr - ly * 10;
                    int gy = ty0 + ly - 1;
                    int gx = tx0 + lx - 1;
                    if ((unsigned)gy < 64u && (unsigned)gx < 64u) {
                        int ac = cin0n + cin_l;
                        const float* src = (ac < CX)
                            ? (xin + ac * NPIX)
                            : (hprev + (ac - CX) * NPIX);
                        v = src[gy * 64 + gx];
                    }
                }
                ist[r] = v;
            }
            for (int d = tid; d < WCNT4; d += 256) {
                int cl_co = d / (CCH * 10);
                int rr = d - cl_co * (CCH * 10);
                const float4* g = wsrc +
                    ((size_t)(co0 + cl_co) * CIN + cin0n) * 10 + rr;
                cp16(smem_u32(reinterpret_cast<float4*>(nbuf + IN_FL) + d), g);
            }
            cp_commit();
        }

        // ---- compute (unroll 2: batch next-iter LDS under current FMAs) --
        const float* wbase = buf + IN_FL + co_l * (CCH * 40) + gp * 20;
        const float* sb = buf + py * SROW + x0;
#pragma unroll 2
        for (int cl = 0; cl < CCH; ++cl) {
            const float* wl = wbase + cl * 40;
            const ulonglong2* wq = reinterpret_cast<const ulonglong2*>(wl);
            ulonglong2 wA = wq[0];
            ulonglong2 wB = wq[1];
            ulonglong2 wC = wq[2];
            ulonglong2 wD = wq[3];
            ull w8 = *reinterpret_cast<const ull*>(wl + 16);
            ull wt0 = wA.x, wt1 = wA.y, wt2 = wB.x;
            ull wt3 = wB.y, wt4 = wC.x, wt5 = wC.y;
            ull wt6 = wD.x, wt7 = wD.y;

            const float* sr = sb + cl * SPLANE;
            {   // ky = 0
                float4 a = *reinterpret_cast<const float4*>(sr);
                float2 b = *reinterpret_cast<const float2*>(sr + 4);
                ull i0 = dup2(a.x), i1 = dup2(a.y), i2 = dup2(a.z);
                ull i3 = dup2(a.w), i4 = dup2(b.x), i5 = dup2(b.y);
                acc[0] = ffma2(i0, wt0, acc[0]);
                acc[1] = ffma2(i1, wt0, acc[1]);
                acc[2] = ffma2(i2, wt0, acc[2]);
                acc[3] = ffma2(i3, wt0, acc[3]);
                acc[0] = ffma2(i1, wt1, acc[0]);
                acc[1] = ffma2(i2, wt1, acc[1]);
                acc[2] = ffma2(i3, wt1, acc[2]);
                acc[3] = ffma2(i4, wt1, acc[3]);
                acc[0] = ffma2(i2, wt2, acc[0]);
                acc[1] = ffma2(i3, wt2, acc[1]);
                acc[2] = ffma2(i4, wt2, acc[2]);
                acc[3] = ffma2(i5, wt2, acc[3]);
            }
            {   // ky = 1
                float4 a = *reinterpret_cast<const float4*>(sr + SROW);
                float2 b = *reinterpret_cast<const float2*>(sr + SROW + 4);
                ull i0 = dup2(a.x), i1 = dup2(a.y), i2 = dup2(a.z);
                ull i3 = dup2(a.w), i4 = dup2(b.x), i5 = dup2(b.y);
                acc[0] = ffma2(i0, wt3, acc[0]);
                acc[1] = ffma2(i1, wt3, acc[1]);
                acc[2] = ffma2(i2, wt3, acc[2]);
                acc[3] = ffma2(i3, wt3, acc[3]);
                acc[0] = ffma2(i1, wt4, acc[0]);
                acc[1] = ffma2(i2, wt4, acc[1]);
                acc[2] = ffma2(i3, wt4, acc[2]);
                acc[3] = ffma2(i4, wt4, acc[3]);
                acc[0] = ffma2(i2, wt5, acc[0]);
                acc[1] = ffma2(i3, wt5, acc[1]);
                acc[2] = ffma2(i4, wt5, acc[2]);
                acc[3] = ffma2(i5, wt5, acc[3]);
            }
            {   // ky = 2
                float4 a = *reinterpret_cast<const float4*>(sr + 2 * SROW);
                float2 b = *reinterpret_cast<const float2*>(sr + 2 * SROW + 4);
                ull i0 = dup2(a.x), i1 = dup2(a.y), i2 = dup2(a.z);
                ull i3 = dup2(a.w), i4 = dup2(b.x), i5 = dup2(b.y);
                acc[0] = ffma2(i0, wt6, acc[0]);
                acc[1] = ffma2(i1, wt6, acc[1]);
                acc[2] = ffma2(i2, wt6, acc[2]);
                acc[3] = ffma2(i3, wt6, acc[3]);
                acc[0] = ffma2(i1, wt7, acc[0]);
                acc[1] = ffma2(i2, wt7, acc[1]);
                acc[2] = ffma2(i3, wt7, acc[2]);
                acc[3] = ffma2(i4, wt7, acc[3]);
                acc[0] = ffma2(i2, w8, acc[0]);
                acc[1] = ffma2(i3, w8, acc[1]);
                acc[2] = ffma2(i4, w8, acc[2]);
                acc[3] = ffma2(i5, w8, acc[3]);
            }
        }

        if (pf) {
            cp_wait0();
#pragma unroll
            for (int r = 0; r < IR; ++r) {
                int idx = tid + r * 256;
                if (idx < ICNT) {
                    int cin_l = idx / HWIN;
                    int rr = idx - cin_l * HWIN;
                    int ly = rr / 10;
                    int lx = rr - ly * 10;
                    nbuf[cin_l * SPLANE + ly * SROW + lx] = ist[r];
                }
            }
        }
        if (NCH > 1) __syncthreads();
    }

    // ---- epilogue: exchange gate pairs within the lane pair ----
    ull oth[4];
#pragma unroll
    for (int j = 0; j < 4; ++j)
        oth[j] = __shfl_xor_sync(0xffffffffu, acc[j], 1);

    const int gy = ty0 + py;
    const int base = co * NPIX + gy * 64 + tx0 + x0 + gp * 2;
    float2 cv = *reinterpret_cast<const float2*>(cst + base);
    float cold[2] = {cv.x, cv.y};
    float cn[2], hv[2];
#pragma unroll
    for (int j2 = 0; j2 < 2; ++j2) {
        int j = gp * 2 + j2;
        float zi, zf, zo, zg;
        if (gp == 0) {
            unpack2(acc[j], zi, zf);
            unpack2(oth[j], zo, zg);
        } else {
            unpack2(oth[j], zi, zf);
            unpack2(acc[j], zo, zg);
        }
        float ig = sigmf(zi);
        float fg = sigmf(zf);
        float og = sigmf(zo);
        float gg = tanh_f(zg);
        float c = fmaf(fg, cold[j2], ig * gg);
        cn[j2] = c;
        hv[j2] = og * tanh_f(c);
    }
    *reinterpret_cast<float2*>(cst + base) = make_float2(cn[0], cn[1]);
    *reinterpret_cast<float2*>(hout + base) = make_float2(hv[0], hv[1]);
}

// ----- standalone step kernels (t=0 L1, t=127 L2) -----
template <int HC, int CIN, int CX, int CCH>
__global__ void __launch_bounds__(256, 3) lstm_step(
    const float* __restrict__ xin, const float* __restrict__ hprev,
    const float* __restrict__ wp, const float* __restrict__ bias,
    float* __restrict__ cst, float* __restrict__ hout)
{
    extern __shared__ float sbuf[];
    lstm_body<HC, CIN, CX, CCH>(blockIdx.x, sbuf, xin, hprev, wp, bias,
                                cst, hout);
}

// ----- fused: blocks [0,512) = L2[t]; [512,768) = L1[t+1] -----
__global__ void __launch_bounds__(256, 3) fused_step(
    const float* __restrict__ ys1_t,
    const float* __restrict__ ys2_prev,
    const float* __restrict__ w2p, const float* __restrict__ b2,
    float* __restrict__ c2, float* __restrict__ ys2_t,
    const float* __restrict__ x_next,
    const float* __restrict__ w1p, const float* __restrict__ b1,
    float* __restrict__ c1, float* __restrict__ ys1_next)
{
    extern __shared__ float sbuf[];
    int bx = blockIdx.x;
    if (bx < 512) {
        lstm_body<64, 96, 32, 16>(bx, sbuf, ys1_t, ys2_prev, w2p, b2,
                                  c2, ys2_t);
    } else {
        lstm_body<32, 35, 3, 35>(bx - 512, sbuf, x_next, ys1_t, w1p, b1,
                                 c1, ys1_next);
    }
}

// ----- FC pass 1: k-chunk partials -----
__global__ void __launch_bounds__(256) fc_part(const float* __restrict__ ys2,
                                               const float* __restrict__ fw,
                                               float* __restrict__ part) {
    __shared__ float red[8][6];
    const int kc = blockIdx.x;
    const int tid = threadIdx.x;
    const int lane = tid & 31;
    const int warp = tid >> 5;
    const int k0 = kc * 4096;
    const int NK = 64 * NPIX;

    for (int t = 0; t < TT; ++t) {
        const float* y = ys2 + (size_t)t * NK + k0;
        float acc[6] = {0.f, 0.f, 0.f, 0.f, 0.f, 0.f};
#pragma unroll 4
        for (int k = tid; k < 4096; k += 256) {
            float v = y[k];
#pragma unroll
            for (int j = 0; j < 6; ++j)
                acc[j] = fmaf(v, fw[(size_t)j * NK + k0 + k], acc[j]);
        }
#pragma unroll
        for (int j = 0; j < 6; ++j) {
#pragma unroll
            for (int off = 16; off > 0; off >>= 1)
                acc[j] += __shfl_xor_sync(0xffffffffu, acc[j], off);
        }
        if (lane < 6) red[warp][lane] = acc[lane];
        __syncthreads();
        if (tid < 6) {
            float s = 0.0f;
#pragma unroll
            for (int w = 0; w < 8; ++w) s += red[w][tid];
            part[(kc * TT + t) * 6 + tid] = s;
        }
        __syncthreads();
    }
}

// ----- FC pass 2 -----
__global__ void fc_reduce(const float* __restrict__ part,
                          const float* __restrict__ fb,
                          float* __restrict__ out) {
    int i = blockIdx.x * blockDim.x + threadIdx.x;
    if (i >= TT * 6) return;
    int j = i % 6;
    float s = fb[j];
    for (int kc = 0; kc < 64; ++kc) s += part[kc * TT * 6 + i];
    out[i] = s;
}

// ----- pack final states -----
__global__ void finalize_kernel(const float* __restrict__ ys1,
                                const float* __restrict__ c1,
                                const float* __restrict__ ys2,
                                const float* __restrict__ c2,
                                float* __restrict__ out) {
    int i = blockIdx.x * blockDim.x + threadIdx.x;
    const int N1 = 32 * NPIX;
    const int N2 = 64 * NPIX;
    if (i < N1) {
        out[768 + i] = ys1[(size_t)(TT - 1) * N1 + i];
    } else if (i < 2 * N1) {
        out[768 + i] = c1[i - N1];
    } else if (i < 2 * N1 + N2) {
        out[768 + i] = ys2[(size_t)(TT - 1) * N2 + (i - 2 * N1)];
    } else if (i < 2 * N1 + 2 * N2) {
        out[768 + i] = c2[i - 2 * N1 - N2];
    }
}

extern "C" void kernel_launch(void* const* d_in, const int* in_sizes, int n_in,
                              void* d_out, int out_size) {
    const float* input = (const float*)d_in[0];
    const float* w1    = (const float*)d_in[1];
    const float* b1    = (const float*)d_in[2];
    const float* w2    = (const float*)d_in[3];
    const float* b2    = (const float*)d_in[4];
    const float* fcw   = (const float*)d_in[5];
    const float* fcb   = (const float*)d_in[6];
    float* out = (float*)d_out;

    float *ys1, *ys2, *c1, *c2, *zb, *w1p, *w2p, *fcpart;
    cudaGetSymbolAddress((void**)&ys1, g_ys1);
    cudaGetSymbolAddress((void**)&ys2, g_ys2);
    cudaGetSymbolAddress((void**)&c1, g_c1);
    cudaGetSymbolAddress((void**)&c2, g_c2);
    cudaGetSymbolAddress((void**)&zb, g_zerobuf);
    cudaGetSymbolAddress((void**)&w1p, g_w1p);
    cudaGetSymbolAddress((void**)&w2p, g_w2p);
    cudaGetSymbolAddress((void**)&fcpart, g_fcpart);

    const int smL1 = (35 * 120 + 8 * 35 * 40) * 4;       // 61600
    const int smL2 = 2 * (16 * 120 + 8 * 16 * 40) * 4;   // 56320
    const int smF = smL1 > smL2 ? smL1 : smL2;
    cudaFuncSetAttribute((const void*)lstm_step<32, 35, 3, 35>,
                         cudaFuncAttributeMaxDynamicSharedMemorySize, smL1);
    cudaFuncSetAttribute((const void*)lstm_step<64, 96, 32, 16>,
                         cudaFuncAttributeMaxDynamicSharedMemorySize, smL2);
    cudaFuncSetAttribute((const void*)fused_step,
                         cudaFuncAttributeMaxDynamicSharedMemorySize, smF);

    const int NSETUP = 32 * NPIX + 3 * 64 * NPIX + 32 * 35 * 40 + 64 * 96 * 40;
    setup_kernel<<<(NSETUP + 255) / 256, 256>>>(w1, w2, w1p, w2p, c1, c2, zb);

    // t = 0 layer 1 (h0 = 0)
    lstm_step<32, 35, 3, 35><<<256, 256, smL1>>>(input, zb, w1p, b1, c1, ys1);

    // fused steps: L2[t] + L1[t+1], t = 0..126
    for (int t = 0; t < TT - 1; ++t) {
        const float* y1t = ys1 + (size_t)t * 32 * NPIX;
        const float* y2p = (t == 0) ? zb : (ys2 + (size_t)(t - 1) * 64 * NPIX);
        float* y2t = ys2 + (size_t)t * 64 * NPIX;
        const float* xn = input + (size_t)(t + 1) * 3 * NPIX;
        float* y1n = ys1 + (size_t)(t + 1) * 32 * NPIX;
        fused_step<<<768, 256, smF>>>(y1t, y2p, w2p, b2, c2, y2t,
                                      xn, w1p, b1, c1, y1n);
    }

    // t = 127 layer 2
    lstm_step<64, 96, 32, 16><<<512, 256, smL2>>>(
        ys1 + (size_t)(TT - 1) * 32 * NPIX,
        ys2 + (size_t)(TT - 2) * 64 * NPIX,
        w2p, b2, c2, ys2 + (size_t)(TT - 1) * 64 * NPIX);

    fc_part<<<64, 256>>>(ys2, fcw, fcpart);
    fc_reduce<<<3, 256>>>(fcpart, fcb, out);

    const int NFIN = 2 * 32 * NPIX + 2 * 64 * NPIX;
    finalize_kernel<<<(NFIN + 255) / 256, 256>>>(ys1, c1, ys2, c2, out);
}